// round 16
// baseline (speedup 1.0000x reference)
#include <cuda_runtime.h>
#include <cuda_bf16.h>
#include <mma.h>
#include <cstdint>
#include <cstddef>

using namespace nvcuda;

// ---------------------------------------------------------------------------
// 2-layer TF LSTM: B=32, T=512, INSZ=HSZ=1024, G=4096.
// Output: concat(out1[32,512,1024], h1[32,1024], c1[32,1024]) f32.
// R16: rec latency trims — publish-early cell phase (h stores + arrive before
//      out_h/state writes), cross-step xz prefetch, staging groups 8->4.
//      Architecture otherwise = R15 (passing, 10.48ms).
// ---------------------------------------------------------------------------

#define BSZ   32
#define TSTEP 512
#define HS    1024
#define GSZ   4096
#define MROWS (BSZ * TSTEP)      // 16384
#define NBLK  128

typedef unsigned long long u64;

// ----------------------------- device scratch ------------------------------
__device__ __align__(16) float g_xproj[(size_t)MROWS * GSZ];
__device__ __align__(16) float g_out0 [(size_t)MROWS * HS];
__device__ __align__(16) __nv_bfloat16 g_hbh[2 * HS * BSZ];   // h hi, [buf][k][b]
__device__ __align__(16) __nv_bfloat16 g_hbl[2 * HS * BSZ];   // h lo
__device__ __align__(16) __nv_bfloat16 g_ah[(size_t)MROWS * HS];
__device__ __align__(16) __nv_bfloat16 g_al[(size_t)MROWS * HS];
__device__ __align__(16) __nv_bfloat16 g_wh[(size_t)HS * GSZ];
__device__ __align__(16) __nv_bfloat16 g_wl[(size_t)HS * GSZ];
__device__ unsigned g_cnt[8];    // per-k-octant producer counters

// ----------------------------- helpers -------------------------------------
__device__ __forceinline__ float sigf(float x) { return 1.0f / (1.0f + __expf(-x)); }

__device__ __forceinline__ void cpasync16(uint32_t s, const void* g) {
    asm volatile("cp.async.cg.shared.global [%0], [%1], 16;"
                 :: "r"(s), "l"(g) : "memory");
}
#define CP_COMMIT() asm volatile("cp.async.commit_group;" ::: "memory")
#define CP_WAIT(n)  asm volatile("cp.async.wait_group %0;" :: "n"(n) : "memory")

__device__ __forceinline__ void stg_cg_u16(unsigned short* p, unsigned short v) {
    asm volatile("st.global.cg.u16 [%0], %1;" :: "l"(p), "h"(v) : "memory");
}

__device__ __forceinline__ void arrive_cnt(unsigned* p) {
    asm volatile("red.release.gpu.global.add.u32 [%0], %1;"
                 :: "l"(p), "r"(1u) : "memory");
}
__device__ __forceinline__ void wait_cnt(const unsigned* p, unsigned target) {
    unsigned v;
    do {
        asm volatile("ld.acquire.gpu.global.u32 %0, [%1];"
                     : "=r"(v) : "l"(p) : "memory");
    } while (v < target);
}

__global__ void init_cnt_kernel() {
    if (threadIdx.x < 8) g_cnt[threadIdx.x] = 0u;
}

// ---------------------------------------------------------------------------
// split_kernel: fp32 -> bf16 hi/lo
// ---------------------------------------------------------------------------
__global__ void __launch_bounds__(256) split_kernel(
    const float* __restrict__ in, __nv_bfloat16* __restrict__ hi,
    __nv_bfloat16* __restrict__ lo)
{
    size_t i = ((size_t)blockIdx.x * 256 + threadIdx.x) * 4;
    float4 v = *(const float4*)(in + i);
    __nv_bfloat16 h0 = __float2bfloat16(v.x);
    __nv_bfloat16 h1 = __float2bfloat16(v.y);
    __nv_bfloat16 h2 = __float2bfloat16(v.z);
    __nv_bfloat16 h3 = __float2bfloat16(v.w);
    __nv_bfloat16 l0 = __float2bfloat16(v.x - __bfloat162float(h0));
    __nv_bfloat16 l1 = __float2bfloat16(v.y - __bfloat162float(h1));
    __nv_bfloat16 l2 = __float2bfloat16(v.z - __bfloat162float(h2));
    __nv_bfloat16 l3 = __float2bfloat16(v.w - __bfloat162float(h3));
    __nv_bfloat162* H = (__nv_bfloat162*)(hi + i);
    __nv_bfloat162* L = (__nv_bfloat162*)(lo + i);
    H[0] = __halves2bfloat162(h0, h1); H[1] = __halves2bfloat162(h2, h3);
    L[0] = __halves2bfloat162(l0, l1); L[1] = __halves2bfloat162(l2, l3);
}

// ---------------------------------------------------------------------------
// mm_kernel (R12, unchanged): C = Ah@Wh + Al@Wh + Ah@Wl + bias
// ---------------------------------------------------------------------------
#define LDA 40
#define LDB 136
#define AT_BYTES (128 * LDA * 2)
#define WT_BYTES (32 * LDB * 2)
#define STAGE    (2 * AT_BYTES + 2 * WT_BYTES)
#define MM_SMEM  (2 * STAGE)

__global__ void __launch_bounds__(256) mm_kernel(
    const __nv_bfloat16* __restrict__ Ah, const __nv_bfloat16* __restrict__ Al,
    const __nv_bfloat16* __restrict__ Bh, const __nv_bfloat16* __restrict__ Bl,
    const float* __restrict__ bias, float* __restrict__ C)
{
    extern __shared__ __align__(128) char smem[];
    __shared__ float biasS[128];

    const int tid = threadIdx.x;
    const int wid = tid >> 5;
    const int wm = wid >> 1, wn = wid & 1;
    const int m0 = blockIdx.y * 128;
    const int n0 = blockIdx.x * 128;

    if (tid < 128) biasS[tid] = bias[n0 + tid];

    uint32_t sbase;
    asm("{ .reg .u64 t; cvta.to.shared.u64 t, %1; cvt.u32.u64 %0, t; }"
        : "=r"(sbase) : "l"(smem));

    const int aR0 = (tid * 2)     >> 2, aC0 = ((tid * 2)     & 3) * 8;
    const int aR1 = (tid * 2 + 1) >> 2, aC1 = ((tid * 2 + 1) & 3) * 8;
    const int wR0 = (tid * 2)     >> 4, wC0 = ((tid * 2)     & 15) * 8;
    const int wR1 = (tid * 2 + 1) >> 4, wC1 = ((tid * 2 + 1) & 15) * 8;

    auto prefetch = [&](int k0, int s) {
        uint32_t st = sbase + s * STAGE;
        uint32_t sAh = st;
        uint32_t sAl = st + AT_BYTES;
        uint32_t sWh = st + 2 * AT_BYTES;
        uint32_t sWl = st + 2 * AT_BYTES + WT_BYTES;
        cpasync16(sAh + (aR0 * LDA + aC0) * 2, Ah + (size_t)(m0 + aR0) * HS + k0 + aC0);
        cpasync16(sAh + (aR1 * LDA + aC1) * 2, Ah + (size_t)(m0 + aR1) * HS + k0 + aC1);
        cpasync16(sAl + (aR0 * LDA + aC0) * 2, Al + (size_t)(m0 + aR0) * HS + k0 + aC0);
        cpasync16(sAl + (aR1 * LDA + aC1) * 2, Al + (size_t)(m0 + aR1) * HS + k0 + aC1);
        cpasync16(sWh + (wR0 * LDB + wC0) * 2, Bh + (size_t)(k0 + wR0) * GSZ + n0 + wC0);
        cpasync16(sWh + (wR1 * LDB + wC1) * 2, Bh + (size_t)(k0 + wR1) * GSZ + n0 + wC1);
        cpasync16(sWl + (wR0 * LDB + wC0) * 2, Bl + (size_t)(k0 + wR0) * GSZ + n0 + wC0);
        cpasync16(sWl + (wR1 * LDB + wC1) * 2, Bl + (size_t)(k0 + wR1) * GSZ + n0 + wC1);
        CP_COMMIT();
    };

    wmma::fragment<wmma::accumulator, 16, 16, 16, float> acc[2][4];
#pragma unroll
    for (int i = 0; i < 2; ++i)
#pragma unroll
        for (int j = 0; j < 4; ++j)
            wmma::fill_fragment(acc[i][j], 0.0f);

    prefetch(0, 0);

#pragma unroll 1
    for (int c = 0; c < 32; ++c) {
        if (c < 31) prefetch((c + 1) * 32, (c + 1) & 1);
        if (c < 31) { CP_WAIT(1); } else { CP_WAIT(0); }
        __syncthreads();

        const char* st = smem + (c & 1) * STAGE;
        const __nv_bfloat16* sAh = (const __nv_bfloat16*)st;
        const __nv_bfloat16* sAl = (const __nv_bfloat16*)(st + AT_BYTES);
        const __nv_bfloat16* sWh = (const __nv_bfloat16*)(st + 2 * AT_BYTES);
        const __nv_bfloat16* sWl = (const __nv_bfloat16*)(st + 2 * AT_BYTES + WT_BYTES);

#pragma unroll
        for (int ks = 0; ks < 2; ++ks) {
            wmma::fragment<wmma::matrix_a, 16, 16, 16, __nv_bfloat16,
                           wmma::row_major> ah[2], al[2];
            wmma::fragment<wmma::matrix_b, 16, 16, 16, __nv_bfloat16,
                           wmma::row_major> wh[4], wl[4];
#pragma unroll
            for (int i = 0; i < 2; ++i) {
                wmma::load_matrix_sync(ah[i],
                    sAh + (size_t)(wm * 32 + i * 16) * LDA + ks * 16, LDA);
                wmma::load_matrix_sync(al[i],
                    sAl + (size_t)(wm * 32 + i * 16) * LDA + ks * 16, LDA);
            }
#pragma unroll
            for (int j = 0; j < 4; ++j) {
                wmma::load_matrix_sync(wh[j],
                    sWh + (size_t)(ks * 16) * LDB + wn * 64 + j * 16, LDB);
                wmma::load_matrix_sync(wl[j],
                    sWl + (size_t)(ks * 16) * LDB + wn * 64 + j * 16, LDB);
            }
#pragma unroll
            for (int i = 0; i < 2; ++i)
#pragma unroll
                for (int j = 0; j < 4; ++j) {
                    wmma::mma_sync(acc[i][j], ah[i], wh[j], acc[i][j]);
                    wmma::mma_sync(acc[i][j], al[i], wh[j], acc[i][j]);
                    wmma::mma_sync(acc[i][j], ah[i], wl[j], acc[i][j]);
                }
        }
        __syncthreads();
    }

    float* Csh = (float*)smem;
#pragma unroll
    for (int i = 0; i < 2; ++i)
#pragma unroll
        for (int j = 0; j < 4; ++j)
            wmma::store_matrix_sync(
                Csh + (size_t)(wm * 32 + i * 16) * 128 + wn * 64 + j * 16,
                acc[i][j], 128, wmma::mem_row_major);
    __syncthreads();

#pragma unroll
    for (int r = 0; r < 16; ++r) {
        int f = tid + r * 256;
        int row = f >> 5, cc = (f & 31) * 4;
        float4 v = *(float4*)(Csh + (size_t)row * 128 + cc);
        v.x += biasS[cc + 0]; v.y += biasS[cc + 1];
        v.z += biasS[cc + 2]; v.w += biasS[cc + 3];
        *(float4*)(C + (size_t)(m0 + row) * GSZ + n0 + cc) = v;
    }
}

// ---------------------------------------------------------------------------
// Recurrence: persistent, 128 CTAs x 256 threads (8 warps).
// z^T[j][b] = Wh^T @ h, wmma bf16 3-term split; W A-frags in registers.
// Octant dataflow counters (R15).  R16: publish-early cell, xz(t+1)
// prefetched during compute, 4 staging commit groups.
// ---------------------------------------------------------------------------
#define R_HST   0                        // 8 warps x 16384 B staging
#define R_ZSH   131072                   // 8 x [32j][32b] f32, 32768 B
#define R_CSH   163840                   // 256 f32
#define R_HOWN  164864                   // 256 f32
#define R_LEN   165888                   // 32 i32
#define REC_SMEM_BYTES 166016

__global__ void __launch_bounds__(256) rec_kernel(
    const float* __restrict__ xproj,
    const float* __restrict__ W,
    const int*   __restrict__ lengths,
    float*       __restrict__ out_h,
    float*       __restrict__ hc_final)
{
    extern __shared__ __align__(128) char sm[];
    float* zsh   = (float*)(sm + R_ZSH);
    float* csh   = (float*)(sm + R_CSH);
    float* hown  = (float*)(sm + R_HOWN);
    int*   lensh = (int*)(sm + R_LEN);

    const int tid  = threadIdx.x;
    const int blk  = blockIdx.x;
    const int w    = tid >> 5;
    const int lane = tid & 31;
    const int oct  = blk >> 4;           // this CTA's producer octant

    uint32_t sbase;
    asm("{ .reg .u64 t; cvta.to.shared.u64 t, %1; cvt.u32.u64 %0, t; }"
        : "=r"(sbase) : "l"(sm));

    // ---- preload W A-fragments into registers (col_major, ldm=32) ----
    wmma::fragment<wmma::matrix_a, 16, 16, 16, __nv_bfloat16,
                   wmma::col_major> fAh[8][2], fAl[8][2];
    {
        __nv_bfloat16* Wtmp = (__nv_bfloat16*)sm;   // 64KB scratch in staging
        for (int i = tid; i < 32768; i += 256) {
            int k = i >> 5, j = i & 31;
            int g = j >> 3, jh = j & 7;
            float v = W[(size_t)(HS + k) * GSZ + g * HS + blk * 8 + jh];
            Wtmp[i] = __float2bfloat16(v);
        }
        __syncthreads();
#pragma unroll
        for (int t = 0; t < 8; ++t)
#pragma unroll
            for (int mt = 0; mt < 2; ++mt)
                wmma::load_matrix_sync(fAh[t][mt],
                    Wtmp + (size_t)(w * 128 + t * 16) * 32 + mt * 16, 32);
        __syncthreads();
        for (int i = tid; i < 32768; i += 256) {
            int k = i >> 5, j = i & 31;
            int g = j >> 3, jh = j & 7;
            float v = W[(size_t)(HS + k) * GSZ + g * HS + blk * 8 + jh];
            __nv_bfloat16 hi = __float2bfloat16(v);
            Wtmp[i] = __float2bfloat16(v - __bfloat162float(hi));
        }
        __syncthreads();
#pragma unroll
        for (int t = 0; t < 8; ++t)
#pragma unroll
            for (int mt = 0; mt < 2; ++mt)
                wmma::load_matrix_sync(fAl[t][mt],
                    Wtmp + (size_t)(w * 128 + t * 16) * 32 + mt * 16, 32);
        __syncthreads();
    }

    if (tid < 32) lensh[tid] = lengths[tid];
    csh[tid] = 0.0f; hown[tid] = 0.0f;
    {   // zero h(0) bf16 slice (buffer 0)
        int k = blk * 8 + w, b = lane;
        stg_cg_u16((unsigned short*)g_hbh + (size_t)k * 32 + b, 0);
        stg_cg_u16((unsigned short*)g_hbl + (size_t)k * 32 + b, 0);
    }
    __syncthreads();
    if (tid == 0) arrive_cnt(&g_cnt[oct]);   // h(0) published

    int cur = 0;
    const uint32_t wst = sbase + R_HST + w * 16384;
    const int bu_c = tid >> 3, jh_c = tid & 7;     // cell-phase coords
    const float* xpbase = xproj + ((size_t)(bu_c * TSTEP)) * GSZ + blk * 8 + jh_c;

    // preload xz(0)
    float xz[4];
#pragma unroll
    for (int g = 0; g < 4; g++) xz[g] = __ldcg(xpbase + g * HS);

    for (int t = 0; t < TSTEP; t++) {
        // wait for this warp's 16 producer CTAs, then issue staging
        if (lane == 0) wait_cnt(&g_cnt[w], 16u * (unsigned)(t + 1));
        __syncwarp();

        const char* srcH = (const char*)(g_hbh + (size_t)cur * 32768 + (size_t)w * 128 * 32);
        const char* srcL = (const char*)(g_hbl + (size_t)cur * 32768 + (size_t)w * 128 * 32);
        // 4 commit groups, 2 tiles (4KB) each
#pragma unroll
        for (int gi = 0; gi < 4; ++gi) {
#pragma unroll
            for (int sub = 0; sub < 2; ++sub) {
                int tt = gi * 2 + sub;
                int o = lane * 32;
                cpasync16(wst + tt * 2048 + o,             srcH + tt * 1024 + o);
                cpasync16(wst + tt * 2048 + o + 16,        srcH + tt * 1024 + o + 16);
                cpasync16(wst + tt * 2048 + 1024 + o,      srcL + tt * 1024 + o);
                cpasync16(wst + tt * 2048 + 1024 + o + 16, srcL + tt * 1024 + o + 16);
            }
            CP_COMMIT();
        }

        wmma::fragment<wmma::accumulator, 16, 16, 16, float> acc[2][2];
#pragma unroll
        for (int i = 0; i < 2; ++i)
#pragma unroll
            for (int j = 0; j < 2; ++j)
                wmma::fill_fragment(acc[i][j], 0.0f);

        float xznext[4];
        bool more = (t < TSTEP - 1);

#pragma unroll
        for (int gi = 0; gi < 4; ++gi) {
            switch (gi) {
                case 0: CP_WAIT(3); break;
                case 1: CP_WAIT(2); break;
                case 2: CP_WAIT(1); break;
                default: CP_WAIT(0); break;
            }
            __syncwarp();

            if (gi == 0 && more) {   // prefetch xz(t+1) in compute shadow
#pragma unroll
                for (int g = 0; g < 4; g++)
                    xznext[g] = __ldcg(xpbase + (size_t)(t + 1) * GSZ + g * HS);
            }

#pragma unroll
            for (int sub = 0; sub < 2; ++sub) {
                int tt = gi * 2 + sub;
                const __nv_bfloat16* Hh =
                    (const __nv_bfloat16*)(sm + R_HST + w * 16384 + tt * 2048);
                const __nv_bfloat16* Hl =
                    (const __nv_bfloat16*)(sm + R_HST + w * 16384 + tt * 2048 + 1024);

                wmma::fragment<wmma::matrix_b, 16, 16, 16, __nv_bfloat16,
                               wmma::row_major> fBh[2], fBl[2];
#pragma unroll
                for (int nt = 0; nt < 2; ++nt) {
                    wmma::load_matrix_sync(fBh[nt], Hh + nt * 16, 32);
                    wmma::load_matrix_sync(fBl[nt], Hl + nt * 16, 32);
                }
#pragma unroll
                for (int mt = 0; mt < 2; ++mt)
#pragma unroll
                    for (int nt = 0; nt < 2; ++nt) {
                        wmma::mma_sync(acc[mt][nt], fAh[tt][mt], fBh[nt], acc[mt][nt]);
                        wmma::mma_sync(acc[mt][nt], fAl[tt][mt], fBh[nt], acc[mt][nt]);
                        wmma::mma_sync(acc[mt][nt], fAh[tt][mt], fBl[nt], acc[mt][nt]);
                    }
            }
        }

        // store warp partials: zsh[w][j][b]
#pragma unroll
        for (int mt = 0; mt < 2; ++mt)
#pragma unroll
            for (int nt = 0; nt < 2; ++nt)
                wmma::store_matrix_sync(
                    zsh + (size_t)w * 1024 + mt * 512 + nt * 16,
                    acc[mt][nt], 32, wmma::mem_row_major);
        __syncthreads();   // all warps' waits passed + partials visible

        // cell update: compute + publish h FIRST, bookkeeping after
        const int nxt = cur ^ 1;
        float hn, hk, ck, cp;
        bool mask;
        {
            float zq[4];
#pragma unroll
            for (int g = 0; g < 4; g++) {
                float s = xz[g];
                int off = (g * 8 + jh_c) * 32 + bu_c;
#pragma unroll
                for (int ww = 0; ww < 8; ww++)
                    s += zsh[ww * 1024 + off];
                zq[g] = s;
            }
            cp = csh[tid];
            float cn = sigf(zq[2] + 1.0f) * cp + sigf(zq[0]) * tanhf(zq[1]);
            hn = sigf(zq[3]) * tanhf(cn);
            mask = (t < lensh[bu_c]);
            hk = mask ? hn : hown[tid];
            ck = mask ? cn : cp;
            // publish h(t+1) immediately
            __nv_bfloat16 hhi = __float2bfloat16(hk);
            __nv_bfloat16 hlo = __float2bfloat16(hk - __bfloat162float(hhi));
            size_t hidx = (size_t)nxt * 32768 + (size_t)(blk * 8 + jh_c) * 32 + bu_c;
            stg_cg_u16((unsigned short*)g_hbh + hidx, *(unsigned short*)&hhi);
            stg_cg_u16((unsigned short*)g_hbl + hidx, *(unsigned short*)&hlo);
        }
        __syncthreads();                       // h stores done CTA-wide
        if (tid == 0) arrive_cnt(&g_cnt[oct]); // release covers them

        // bookkeeping in the shadow of the next wait
        {
            csh[tid]  = ck;
            hown[tid] = hk;
            int kg = blk * 8 + jh_c;
            out_h[((size_t)bu_c * TSTEP + t) * HS + kg] = mask ? hn : 0.0f;
            if (hc_final != nullptr && t == TSTEP - 1) {
                hc_final[(size_t)bu_c * HS + kg]         = hk;
                hc_final[32768 + (size_t)bu_c * HS + kg] = ck;
            }
#pragma unroll
            for (int g = 0; g < 4; g++) xz[g] = xznext[g];
        }
        // csh/hown races: written here, read next step AFTER the partials
        // __syncthreads() -> safe.
        cur = nxt;
    }
}

// ---------------------------------------------------------------------------
extern "C" void kernel_launch(void* const* d_in, const int* in_sizes, int n_in,
                              void* d_out, int out_size)
{
    const float* x       = (const float*)d_in[0];
    const int*   lengths = (const int*)  d_in[1];
    const float* W0      = (const float*)d_in[2];
    const float* b0      = (const float*)d_in[3];
    const float* W1      = (const float*)d_in[4];
    const float* b1      = (const float*)d_in[5];
    float*       out     = (float*)d_out;

    (void)in_sizes; (void)n_in; (void)out_size;

    cudaFuncSetAttribute(rec_kernel,
                         cudaFuncAttributeMaxDynamicSharedMemorySize,
                         REC_SMEM_BYTES);
    cudaFuncSetAttribute(mm_kernel,
                         cudaFuncAttributeMaxDynamicSharedMemorySize,
                         MM_SMEM);

    float* xproj = nullptr;
    float* out0  = nullptr;
    __nv_bfloat16 *ah, *al, *wh, *wl;
    cudaGetSymbolAddress((void**)&xproj, g_xproj);
    cudaGetSymbolAddress((void**)&out0,  g_out0);
    cudaGetSymbolAddress((void**)&ah, g_ah);
    cudaGetSymbolAddress((void**)&al, g_al);
    cudaGetSymbolAddress((void**)&wh, g_wh);
    cudaGetSymbolAddress((void**)&wl, g_wl);

    dim3 mgrid(GSZ / 128, MROWS / 128);   // (32, 128)

    // Layer 0
    split_kernel<<<(MROWS * HS) / 1024, 256>>>(x, ah, al);
    split_kernel<<<(HS * GSZ) / 1024, 256>>>(W0, wh, wl);
    mm_kernel<<<mgrid, 256, MM_SMEM>>>(ah, al, wh, wl, b0, xproj);
    init_cnt_kernel<<<1, 32>>>();
    rec_kernel<<<NBLK, 256, REC_SMEM_BYTES>>>(xproj, W0, lengths, out0, nullptr);

    // Layer 1
    split_kernel<<<(MROWS * HS) / 1024, 256>>>(out0, ah, al);
    split_kernel<<<(HS * GSZ) / 1024, 256>>>(W1, wh, wl);
    mm_kernel<<<mgrid, 256, MM_SMEM>>>(ah, al, wh, wl, b1, xproj);
    init_cnt_kernel<<<1, 32>>>();
    rec_kernel<<<NBLK, 256, REC_SMEM_BYTES>>>(xproj, W1, lengths,
                                              out, out + (size_t)MROWS * HS);
}

// round 17
// speedup vs baseline: 1.0727x; 1.0727x over previous
#include <cuda_runtime.h>
#include <cuda_bf16.h>
#include <mma.h>
#include <cstdint>
#include <cstddef>

using namespace nvcuda;

// ---------------------------------------------------------------------------
// 2-layer TF LSTM: B=32, T=512, INSZ=HSZ=1024, G=4096.
// Output: concat(out1[32,512,1024], h1[32,1024], c1[32,1024]) f32.
// R17: base R15 + (1) warp-granular cell/publish: warp w owns gate column
//      blk*8+w (lane=batch), per-warp counter arrivals (128/step), no
//      end-of-step CTA sync; zsh/xsh parity double-buffered.
//      (2) rec0 emits bf16 hi/lo xproj input directly (split fused).
// ---------------------------------------------------------------------------

#define BSZ   32
#define TSTEP 512
#define HS    1024
#define GSZ   4096
#define MROWS (BSZ * TSTEP)      // 16384
#define NBLK  128

typedef unsigned long long u64;

// ----------------------------- device scratch ------------------------------
__device__ __align__(16) float g_xproj[(size_t)MROWS * GSZ];
__device__ __align__(16) __nv_bfloat16 g_hbh[2 * HS * BSZ];   // h hi, [buf][k][b]
__device__ __align__(16) __nv_bfloat16 g_hbl[2 * HS * BSZ];   // h lo
__device__ __align__(16) __nv_bfloat16 g_ah[(size_t)MROWS * HS];
__device__ __align__(16) __nv_bfloat16 g_al[(size_t)MROWS * HS];
__device__ __align__(16) __nv_bfloat16 g_wh[(size_t)HS * GSZ];
__device__ __align__(16) __nv_bfloat16 g_wl[(size_t)HS * GSZ];
__device__ unsigned g_cnt[8];    // per-k-octant producer counters

// ----------------------------- helpers -------------------------------------
__device__ __forceinline__ float sigf(float x) { return 1.0f / (1.0f + __expf(-x)); }

__device__ __forceinline__ void cpasync16(uint32_t s, const void* g) {
    asm volatile("cp.async.cg.shared.global [%0], [%1], 16;"
                 :: "r"(s), "l"(g) : "memory");
}
#define CP_COMMIT() asm volatile("cp.async.commit_group;" ::: "memory")
#define CP_WAIT(n)  asm volatile("cp.async.wait_group %0;" :: "n"(n) : "memory")

__device__ __forceinline__ void stg_cg_u16(unsigned short* p, unsigned short v) {
    asm volatile("st.global.cg.u16 [%0], %1;" :: "l"(p), "h"(v) : "memory");
}

__device__ __forceinline__ void arrive_cnt(unsigned* p) {
    asm volatile("red.release.gpu.global.add.u32 [%0], %1;"
                 :: "l"(p), "r"(1u) : "memory");
}
__device__ __forceinline__ void wait_cnt(const unsigned* p, unsigned target) {
    unsigned v;
    do {
        asm volatile("ld.acquire.gpu.global.u32 %0, [%1];"
                     : "=r"(v) : "l"(p) : "memory");
    } while (v < target);
}

__global__ void init_cnt_kernel() {
    if (threadIdx.x < 8) g_cnt[threadIdx.x] = 0u;
}

// ---------------------------------------------------------------------------
// split_kernel: fp32 -> bf16 hi/lo
// ---------------------------------------------------------------------------
__global__ void __launch_bounds__(256) split_kernel(
    const float* __restrict__ in, __nv_bfloat16* __restrict__ hi,
    __nv_bfloat16* __restrict__ lo)
{
    size_t i = ((size_t)blockIdx.x * 256 + threadIdx.x) * 4;
    float4 v = *(const float4*)(in + i);
    __nv_bfloat16 h0 = __float2bfloat16(v.x);
    __nv_bfloat16 h1 = __float2bfloat16(v.y);
    __nv_bfloat16 h2 = __float2bfloat16(v.z);
    __nv_bfloat16 h3 = __float2bfloat16(v.w);
    __nv_bfloat16 l0 = __float2bfloat16(v.x - __bfloat162float(h0));
    __nv_bfloat16 l1 = __float2bfloat16(v.y - __bfloat162float(h1));
    __nv_bfloat16 l2 = __float2bfloat16(v.z - __bfloat162float(h2));
    __nv_bfloat16 l3 = __float2bfloat16(v.w - __bfloat162float(h3));
    __nv_bfloat162* H = (__nv_bfloat162*)(hi + i);
    __nv_bfloat162* L = (__nv_bfloat162*)(lo + i);
    H[0] = __halves2bfloat162(h0, h1); H[1] = __halves2bfloat162(h2, h3);
    L[0] = __halves2bfloat162(l0, l1); L[1] = __halves2bfloat162(l2, l3);
}

// ---------------------------------------------------------------------------
// mm_kernel (R12, unchanged): C = Ah@Wh + Al@Wh + Ah@Wl + bias
// ---------------------------------------------------------------------------
#define LDA 40
#define LDB 136
#define AT_BYTES (128 * LDA * 2)
#define WT_BYTES (32 * LDB * 2)
#define STAGE    (2 * AT_BYTES + 2 * WT_BYTES)
#define MM_SMEM  (2 * STAGE)

__global__ void __launch_bounds__(256) mm_kernel(
    const __nv_bfloat16* __restrict__ Ah, const __nv_bfloat16* __restrict__ Al,
    const __nv_bfloat16* __restrict__ Bh, const __nv_bfloat16* __restrict__ Bl,
    const float* __restrict__ bias, float* __restrict__ C)
{
    extern __shared__ __align__(128) char smem[];
    __shared__ float biasS[128];

    const int tid = threadIdx.x;
    const int wid = tid >> 5;
    const int wm = wid >> 1, wn = wid & 1;
    const int m0 = blockIdx.y * 128;
    const int n0 = blockIdx.x * 128;

    if (tid < 128) biasS[tid] = bias[n0 + tid];

    uint32_t sbase;
    asm("{ .reg .u64 t; cvta.to.shared.u64 t, %1; cvt.u32.u64 %0, t; }"
        : "=r"(sbase) : "l"(smem));

    const int aR0 = (tid * 2)     >> 2, aC0 = ((tid * 2)     & 3) * 8;
    const int aR1 = (tid * 2 + 1) >> 2, aC1 = ((tid * 2 + 1) & 3) * 8;
    const int wR0 = (tid * 2)     >> 4, wC0 = ((tid * 2)     & 15) * 8;
    const int wR1 = (tid * 2 + 1) >> 4, wC1 = ((tid * 2 + 1) & 15) * 8;

    auto prefetch = [&](int k0, int s) {
        uint32_t st = sbase + s * STAGE;
        uint32_t sAh = st;
        uint32_t sAl = st + AT_BYTES;
        uint32_t sWh = st + 2 * AT_BYTES;
        uint32_t sWl = st + 2 * AT_BYTES + WT_BYTES;
        cpasync16(sAh + (aR0 * LDA + aC0) * 2, Ah + (size_t)(m0 + aR0) * HS + k0 + aC0);
        cpasync16(sAh + (aR1 * LDA + aC1) * 2, Ah + (size_t)(m0 + aR1) * HS + k0 + aC1);
        cpasync16(sAl + (aR0 * LDA + aC0) * 2, Al + (size_t)(m0 + aR0) * HS + k0 + aC0);
        cpasync16(sAl + (aR1 * LDA + aC1) * 2, Al + (size_t)(m0 + aR1) * HS + k0 + aC1);
        cpasync16(sWh + (wR0 * LDB + wC0) * 2, Bh + (size_t)(k0 + wR0) * GSZ + n0 + wC0);
        cpasync16(sWh + (wR1 * LDB + wC1) * 2, Bh + (size_t)(k0 + wR1) * GSZ + n0 + wC1);
        cpasync16(sWl + (wR0 * LDB + wC0) * 2, Bl + (size_t)(k0 + wR0) * GSZ + n0 + wC0);
        cpasync16(sWl + (wR1 * LDB + wC1) * 2, Bl + (size_t)(k0 + wR1) * GSZ + n0 + wC1);
        CP_COMMIT();
    };

    wmma::fragment<wmma::accumulator, 16, 16, 16, float> acc[2][4];
#pragma unroll
    for (int i = 0; i < 2; ++i)
#pragma unroll
        for (int j = 0; j < 4; ++j)
            wmma::fill_fragment(acc[i][j], 0.0f);

    prefetch(0, 0);

#pragma unroll 1
    for (int c = 0; c < 32; ++c) {
        if (c < 31) prefetch((c + 1) * 32, (c + 1) & 1);
        if (c < 31) { CP_WAIT(1); } else { CP_WAIT(0); }
        __syncthreads();

        const char* st = smem + (c & 1) * STAGE;
        const __nv_bfloat16* sAh = (const __nv_bfloat16*)st;
        const __nv_bfloat16* sAl = (const __nv_bfloat16*)(st + AT_BYTES);
        const __nv_bfloat16* sWh = (const __nv_bfloat16*)(st + 2 * AT_BYTES);
        const __nv_bfloat16* sWl = (const __nv_bfloat16*)(st + 2 * AT_BYTES + WT_BYTES);

#pragma unroll
        for (int ks = 0; ks < 2; ++ks) {
            wmma::fragment<wmma::matrix_a, 16, 16, 16, __nv_bfloat16,
                           wmma::row_major> ah[2], al[2];
            wmma::fragment<wmma::matrix_b, 16, 16, 16, __nv_bfloat16,
                           wmma::row_major> wh[4], wl[4];
#pragma unroll
            for (int i = 0; i < 2; ++i) {
                wmma::load_matrix_sync(ah[i],
                    sAh + (size_t)(wm * 32 + i * 16) * LDA + ks * 16, LDA);
                wmma::load_matrix_sync(al[i],
                    sAl + (size_t)(wm * 32 + i * 16) * LDA + ks * 16, LDA);
            }
#pragma unroll
            for (int j = 0; j < 4; ++j) {
                wmma::load_matrix_sync(wh[j],
                    sWh + (size_t)(ks * 16) * LDB + wn * 64 + j * 16, LDB);
                wmma::load_matrix_sync(wl[j],
                    sWl + (size_t)(ks * 16) * LDB + wn * 64 + j * 16, LDB);
            }
#pragma unroll
            for (int i = 0; i < 2; ++i)
#pragma unroll
                for (int j = 0; j < 4; ++j) {
                    wmma::mma_sync(acc[i][j], ah[i], wh[j], acc[i][j]);
                    wmma::mma_sync(acc[i][j], al[i], wh[j], acc[i][j]);
                    wmma::mma_sync(acc[i][j], ah[i], wl[j], acc[i][j]);
                }
        }
        __syncthreads();
    }

    float* Csh = (float*)smem;
#pragma unroll
    for (int i = 0; i < 2; ++i)
#pragma unroll
        for (int j = 0; j < 4; ++j)
            wmma::store_matrix_sync(
                Csh + (size_t)(wm * 32 + i * 16) * 128 + wn * 64 + j * 16,
                acc[i][j], 128, wmma::mem_row_major);
    __syncthreads();

#pragma unroll
    for (int r = 0; r < 16; ++r) {
        int f = tid + r * 256;
        int row = f >> 5, cc = (f & 31) * 4;
        float4 v = *(float4*)(Csh + (size_t)row * 128 + cc);
        v.x += biasS[cc + 0]; v.y += biasS[cc + 1];
        v.z += biasS[cc + 2]; v.w += biasS[cc + 3];
        *(float4*)(C + (size_t)(m0 + row) * GSZ + n0 + cc) = v;
    }
}

// ---------------------------------------------------------------------------
// Recurrence: persistent, 128 CTAs x 256 threads (8 warps).
// z^T[j][b] = Wh^T @ h, wmma bf16 3-term split; W A-frags in registers;
// octant dataflow counters with PER-WARP arrivals (128/step per octant).
// Warp w: k in [128w,128w+128) for mma; cell phase = gate column blk*8+w,
// lane = batch.  One __syncthreads per step (partials).  zsh/xsh parity
// double-buffered; csh/hown thread-private.
// ---------------------------------------------------------------------------
#define R_HST   0                        // 8 warps x 16384 B staging
#define R_ZSH   131072                   // 2 x 8 x 1024 f32 = 65536 B
#define R_XSH   196608                   // 2 x 4 x 288 f32 = 9216 B
#define R_CSH   205824                   // 256 f32
#define R_HOWN  206848                   // 256 f32
#define R_LEN   207872                   // 32 i32
#define REC_SMEM_BYTES 208000

__global__ void __launch_bounds__(256) rec_kernel(
    const float* __restrict__ xproj,
    const float* __restrict__ W,
    const int*   __restrict__ lengths,
    float*       __restrict__ out_h,     // fp32 out (layer 1) or null
    __nv_bfloat16* __restrict__ outbh,   // bf16-hi out (layer 0) or null
    __nv_bfloat16* __restrict__ outbl,   // bf16-lo out (layer 0) or null
    float*       __restrict__ hc_final)  // [h1|c1] (layer 1) or null
{
    extern __shared__ __align__(128) char sm[];
    float* zsh   = (float*)(sm + R_ZSH);   // [par][ww][j*32+b]
    float* xsh   = (float*)(sm + R_XSH);   // [par][g][bu*9+jh]
    float* csh   = (float*)(sm + R_CSH);
    float* hown  = (float*)(sm + R_HOWN);
    int*   lensh = (int*)(sm + R_LEN);

    const int tid  = threadIdx.x;
    const int blk  = blockIdx.x;
    const int w    = tid >> 5;
    const int lane = tid & 31;
    const int oct  = blk >> 4;           // this CTA's producer octant

    uint32_t sbase;
    asm("{ .reg .u64 t; cvta.to.shared.u64 t, %1; cvt.u32.u64 %0, t; }"
        : "=r"(sbase) : "l"(sm));

    // ---- preload W A-fragments into registers (col_major, ldm=32) ----
    wmma::fragment<wmma::matrix_a, 16, 16, 16, __nv_bfloat16,
                   wmma::col_major> fAh[8][2], fAl[8][2];
    {
        __nv_bfloat16* Wtmp = (__nv_bfloat16*)sm;   // 64KB scratch in staging
        for (int i = tid; i < 32768; i += 256) {
            int k = i >> 5, j = i & 31;
            int g = j >> 3, jh = j & 7;
            float v = W[(size_t)(HS + k) * GSZ + g * HS + blk * 8 + jh];
            Wtmp[i] = __float2bfloat16(v);
        }
        __syncthreads();
#pragma unroll
        for (int t = 0; t < 8; ++t)
#pragma unroll
            for (int mt = 0; mt < 2; ++mt)
                wmma::load_matrix_sync(fAh[t][mt],
                    Wtmp + (size_t)(w * 128 + t * 16) * 32 + mt * 16, 32);
        __syncthreads();
        for (int i = tid; i < 32768; i += 256) {
            int k = i >> 5, j = i & 31;
            int g = j >> 3, jh = j & 7;
            float v = W[(size_t)(HS + k) * GSZ + g * HS + blk * 8 + jh];
            __nv_bfloat16 hi = __float2bfloat16(v);
            Wtmp[i] = __float2bfloat16(v - __bfloat162float(hi));
        }
        __syncthreads();
#pragma unroll
        for (int t = 0; t < 8; ++t)
#pragma unroll
            for (int mt = 0; mt < 2; ++mt)
                wmma::load_matrix_sync(fAl[t][mt],
                    Wtmp + (size_t)(w * 128 + t * 16) * 32 + mt * 16, 32);
        __syncthreads();
    }

    if (tid < 32) lensh[tid] = lengths[tid];
    csh[tid] = 0.0f; hown[tid] = 0.0f;   // thread-private state (col w, batch lane)
    {   // warp w zeroes its h(0) column slice, then per-warp arrive
        size_t hidx = (size_t)(blk * 8 + w) * 32 + lane;
        stg_cg_u16((unsigned short*)g_hbh + hidx, 0);
        stg_cg_u16((unsigned short*)g_hbl + hidx, 0);
        __syncwarp();
        if (lane == 0) arrive_cnt(&g_cnt[oct]);
    }

    int cur = 0;
    const uint32_t wst = sbase + R_HST + w * 16384;
    const int bu_x = tid >> 3, jh_x = tid & 7;     // xz load coords

    for (int t = 0; t < TSTEP; t++) {
        const int par = t & 1;

        // coalesced xz loads -> xsh exchange (read in cell after partials sync)
        {
            const float* xp =
                xproj + ((size_t)(bu_x * TSTEP + t)) * GSZ + blk * 8 + jh_x;
#pragma unroll
            for (int g = 0; g < 4; g++)
                xsh[par * 1152 + g * 288 + bu_x * 9 + jh_x] = __ldcg(xp + g * HS);
        }

        // wait for this warp's producers (128 warp-arrives * (t+1))
        if (lane == 0) wait_cnt(&g_cnt[w], 128u * (unsigned)(t + 1));
        __syncwarp();

        const char* srcH = (const char*)(g_hbh + (size_t)cur * 32768 + (size_t)w * 128 * 32);
        const char* srcL = (const char*)(g_hbl + (size_t)cur * 32768 + (size_t)w * 128 * 32);
#pragma unroll
        for (int tt = 0; tt < 8; ++tt) {
            int o = lane * 32;   // 2x16B per lane
            cpasync16(wst + tt * 2048 + o,             srcH + tt * 1024 + o);
            cpasync16(wst + tt * 2048 + o + 16,        srcH + tt * 1024 + o + 16);
            cpasync16(wst + tt * 2048 + 1024 + o,      srcL + tt * 1024 + o);
            cpasync16(wst + tt * 2048 + 1024 + o + 16, srcL + tt * 1024 + o + 16);
            CP_COMMIT();
        }

        wmma::fragment<wmma::accumulator, 16, 16, 16, float> acc[2][2];
#pragma unroll
        for (int i = 0; i < 2; ++i)
#pragma unroll
            for (int j = 0; j < 2; ++j)
                wmma::fill_fragment(acc[i][j], 0.0f);

#pragma unroll
        for (int tt = 0; tt < 8; ++tt) {
            switch (tt) {
                case 0: CP_WAIT(7); break;
                case 1: CP_WAIT(6); break;
                case 2: CP_WAIT(5); break;
                case 3: CP_WAIT(4); break;
                case 4: CP_WAIT(3); break;
                case 5: CP_WAIT(2); break;
                case 6: CP_WAIT(1); break;
                default: CP_WAIT(0); break;
            }
            __syncwarp();

            const __nv_bfloat16* Hh =
                (const __nv_bfloat16*)(sm + R_HST + w * 16384 + tt * 2048);
            const __nv_bfloat16* Hl =
                (const __nv_bfloat16*)(sm + R_HST + w * 16384 + tt * 2048 + 1024);

            wmma::fragment<wmma::matrix_b, 16, 16, 16, __nv_bfloat16,
                           wmma::row_major> fBh[2], fBl[2];
#pragma unroll
            for (int nt = 0; nt < 2; ++nt) {
                wmma::load_matrix_sync(fBh[nt], Hh + nt * 16, 32);
                wmma::load_matrix_sync(fBl[nt], Hl + nt * 16, 32);
            }
#pragma unroll
            for (int mt = 0; mt < 2; ++mt)
#pragma unroll
                for (int nt = 0; nt < 2; ++nt) {
                    wmma::mma_sync(acc[mt][nt], fAh[tt][mt], fBh[nt], acc[mt][nt]);
                    wmma::mma_sync(acc[mt][nt], fAl[tt][mt], fBh[nt], acc[mt][nt]);
                    wmma::mma_sync(acc[mt][nt], fAh[tt][mt], fBl[nt], acc[mt][nt]);
                }
        }

        // store warp partials into parity buffer: zsh[par][w][j][b]
#pragma unroll
        for (int mt = 0; mt < 2; ++mt)
#pragma unroll
            for (int nt = 0; nt < 2; ++nt)
                wmma::store_matrix_sync(
                    zsh + (size_t)par * 8192 + (size_t)w * 1024 + mt * 512 + nt * 16,
                    acc[mt][nt], 32, wmma::mem_row_major);
        __syncthreads();   // the ONLY CTA-wide sync per step

        // cell phase: warp w = gate column blk*8+w, lane = batch
        const int nxt = cur ^ 1;
        {
            float zq[4];
#pragma unroll
            for (int g = 0; g < 4; g++) {
                float s = xsh[par * 1152 + g * 288 + lane * 9 + w];
                int off = (g * 8 + w) * 32 + lane;
                const float* zp = zsh + (size_t)par * 8192 + off;
#pragma unroll
                for (int ww = 0; ww < 8; ww++)
                    s += zp[ww * 1024];
                zq[g] = s;
            }
            float cp = csh[tid];
            float cn = sigf(zq[2] + 1.0f) * cp + sigf(zq[0]) * tanhf(zq[1]);
            float hn = sigf(zq[3]) * tanhf(cn);
            bool mask = (t < lensh[lane]);
            float hk = mask ? hn : hown[tid];
            float ck = mask ? cn : cp;

            // publish h(t+1) slice immediately (64B-contiguous per warp)
            __nv_bfloat16 hhi = __float2bfloat16(hk);
            __nv_bfloat16 hlo = __float2bfloat16(hk - __bfloat162float(hhi));
            size_t hidx = (size_t)nxt * 32768 + (size_t)(blk * 8 + w) * 32 + lane;
            stg_cg_u16((unsigned short*)g_hbh + hidx, *(unsigned short*)&hhi);
            stg_cg_u16((unsigned short*)g_hbl + hidx, *(unsigned short*)&hlo);
            __syncwarp();
            if (lane == 0) arrive_cnt(&g_cnt[oct]);

            // bookkeeping in the shadow of the next wait
            csh[tid]  = ck;
            hown[tid] = hk;
            float ho = mask ? hn : 0.0f;
            size_t oidx = ((size_t)lane * TSTEP + t) * HS + blk * 8 + w;
            if (out_h != nullptr) out_h[oidx] = ho;
            if (outbh != nullptr) {
                __nv_bfloat16 oh = __float2bfloat16(ho);
                __nv_bfloat16 ol = __float2bfloat16(ho - __bfloat162float(oh));
                outbh[oidx] = oh;
                outbl[oidx] = ol;
            }
            if (hc_final != nullptr && t == TSTEP - 1) {
                hc_final[(size_t)lane * HS + blk * 8 + w]         = hk;
                hc_final[32768 + (size_t)lane * HS + blk * 8 + w] = ck;
            }
        }
        cur = nxt;
    }
}

// ---------------------------------------------------------------------------
extern "C" void kernel_launch(void* const* d_in, const int* in_sizes, int n_in,
                              void* d_out, int out_size)
{
    const float* x       = (const float*)d_in[0];
    const int*   lengths = (const int*)  d_in[1];
    const float* W0      = (const float*)d_in[2];
    const float* b0      = (const float*)d_in[3];
    const float* W1      = (const float*)d_in[4];
    const float* b1      = (const float*)d_in[5];
    float*       out     = (float*)d_out;

    (void)in_sizes; (void)n_in; (void)out_size;

    cudaFuncSetAttribute(rec_kernel,
                         cudaFuncAttributeMaxDynamicSharedMemorySize,
                         REC_SMEM_BYTES);
    cudaFuncSetAttribute(mm_kernel,
                         cudaFuncAttributeMaxDynamicSharedMemorySize,
                         MM_SMEM);

    float* xproj = nullptr;
    __nv_bfloat16 *ah, *al, *wh, *wl;
    cudaGetSymbolAddress((void**)&xproj, g_xproj);
    cudaGetSymbolAddress((void**)&ah, g_ah);
    cudaGetSymbolAddress((void**)&al, g_al);
    cudaGetSymbolAddress((void**)&wh, g_wh);
    cudaGetSymbolAddress((void**)&wl, g_wl);

    dim3 mgrid(GSZ / 128, MROWS / 128);   // (32, 128)

    // Layer 0: rec writes bf16 hi/lo (layer-1 mm input) directly
    split_kernel<<<(MROWS * HS) / 1024, 256>>>(x, ah, al);
    split_kernel<<<(HS * GSZ) / 1024, 256>>>(W0, wh, wl);
    mm_kernel<<<mgrid, 256, MM_SMEM>>>(ah, al, wh, wl, b0, xproj);
    init_cnt_kernel<<<1, 32>>>();
    rec_kernel<<<NBLK, 256, REC_SMEM_BYTES>>>(xproj, W0, lengths,
                                              nullptr, ah, al, nullptr);

    // Layer 1
    split_kernel<<<(HS * GSZ) / 1024, 256>>>(W1, wh, wl);
    mm_kernel<<<mgrid, 256, MM_SMEM>>>(ah, al, wh, wl, b1, xproj);
    init_cnt_kernel<<<1, 32>>>();
    rec_kernel<<<NBLK, 256, REC_SMEM_BYTES>>>(xproj, W1, lengths,
                                              out, nullptr, nullptr,
                                              out + (size_t)MROWS * HS);
}